// round 11
// baseline (speedup 1.0000x reference)
#include <cuda_runtime.h>
#include <cuda_bf16.h>
#include <math.h>
#include <stdint.h>

// Problem constants
#define BB   4
#define LL   1024
#define DD   1024
#define NH   16
#define HH   64
#define RR   2048
#define LOG2E 1.4426950408889634f
#define KBYTES 2048        // K=1024 bf16 row stride in bytes

// ---------------------------------------------------------------------------
// Device scratch
// ---------------------------------------------------------------------------
__device__ uint4 g_INhi4[BB * LL * DD / 8];   // 8 MB
__device__ uint4 g_INlo4[BB * LL * DD / 8];
__device__ uint4 g_WThi4[DD * DD / 8];        // 2 MB, [n][k]
__device__ uint4 g_WTlo4[DD * DD / 8];

__device__ uint32_t g_QHh2[BB * NH * LL * HH / 2];   // qh (no bias)
__device__ uint32_t g_QHl2[BB * NH * LL * HH / 2];
__device__ uint32_t g_KHh2[BB * NH * LL * HH / 2];
__device__ uint32_t g_KHl2[BB * NH * LL * HH / 2];
__device__ uint32_t g_VHh2[BB * NH * LL * HH / 2];
__device__ uint32_t g_VHl2[BB * NH * LL * HH / 2];
__device__ uint32_t g_RPh2[NH * RR * HH / 2];
__device__ uint32_t g_RPl2[NH * RR * HH / 2];
__device__ float    g_C1[BB * NH * LL];              // r_w_bias . kh
__device__ float    g_C2[NH * RR];                   // r_r_bias . r

__device__ __forceinline__ uint32_t smem_u32(const void* p) {
    uint32_t a;
    asm("{ .reg .u64 t; cvta.to.shared.u64 t, %1; cvt.u32.u64 %0, t; }" : "=r"(a) : "l"(p));
    return a;
}
__device__ __forceinline__ void ldmx4(uint32_t* r, uint32_t addr) {
    asm volatile("ldmatrix.sync.aligned.m8n8.x4.shared.b16 {%0,%1,%2,%3}, [%4];"
        : "=r"(r[0]), "=r"(r[1]), "=r"(r[2]), "=r"(r[3]) : "r"(addr));
}
__device__ __forceinline__ void ldmx4t(uint32_t* r, uint32_t addr) {
    asm volatile("ldmatrix.sync.aligned.m8n8.x4.trans.shared.b16 {%0,%1,%2,%3}, [%4];"
        : "=r"(r[0]), "=r"(r[1]), "=r"(r[2]), "=r"(r[3]) : "r"(addr));
}
__device__ __forceinline__ void mma16816(float* c, const uint32_t* a, const uint32_t* b) {
    asm volatile("mma.sync.aligned.m16n8k16.row.col.f32.bf16.bf16.f32 "
        "{%0,%1,%2,%3}, {%4,%5,%6,%7}, {%8,%9}, {%0,%1,%2,%3};"
        : "+f"(c[0]), "+f"(c[1]), "+f"(c[2]), "+f"(c[3])
        : "r"(a[0]), "r"(a[1]), "r"(a[2]), "r"(a[3]), "r"(b[0]), "r"(b[1]));
}
#define CPA16(dst, src) \
    asm volatile("cp.async.cg.shared.global [%0], [%1], 16;" :: "r"(dst), "l"(src) : "memory")
#define CP_COMMIT() asm volatile("cp.async.commit_group;" ::: "memory")
#define CP_WAIT(n)  asm volatile("cp.async.wait_group %0;" :: "n"(n) : "memory")

__device__ __forceinline__ void pack_hilo(float a, float b, uint32_t& hi, uint32_t& lo) {
    __nv_bfloat16 ha = __float2bfloat16_rn(a), hb = __float2bfloat16_rn(b);
    __nv_bfloat162 h2; h2.x = ha; h2.y = hb;
    __nv_bfloat162 l2;
    l2.x = __float2bfloat16_rn(a - __bfloat162float(ha));
    l2.y = __float2bfloat16_rn(b - __bfloat162float(hb));
    hi = *(uint32_t*)&h2; lo = *(uint32_t*)&l2;
}
__device__ __forceinline__ uint32_t pack_bf2(float a, float b) {
    __nv_bfloat162 h2; h2.x = __float2bfloat16_rn(a); h2.y = __float2bfloat16_rn(b);
    return *(uint32_t*)&h2;
}
// exp2 on FMA pipe: deg-5 poly + exponent splice.  arg <= 0, clamped at -125.
__device__ __forceinline__ float exp2p(float t) {
    t = fmaxf(t, -125.0f);
    float tr = t + 12582912.0f;
    int   n  = __float_as_int(tr) - 0x4B400000;
    float f  = t - (tr - 12582912.0f);
    float p  = 1.3333558146e-3f;
    p = fmaf(p, f, 9.6181291076e-3f);
    p = fmaf(p, f, 5.5504108665e-2f);
    p = fmaf(p, f, 2.4022650696e-1f);
    p = fmaf(p, f, 6.9314718056e-1f);
    p = fmaf(p, f, 1.0f);
    return __int_as_float(__float_as_int(p) + (n << 23));
}

// ---------------------------------------------------------------------------
// Prepasses
// ---------------------------------------------------------------------------
__global__ __launch_bounds__(256) void cvt_kernel(const float4* __restrict__ src,
                                                  uint32_t* __restrict__ hi,
                                                  uint32_t* __restrict__ lo, int n4)
{
    int i = blockIdx.x * 256 + threadIdx.x;
    if (i >= n4) return;
    float4 x = src[i];
    uint32_t h0, l0, h1, l1;
    pack_hilo(x.x, x.y, h0, l0);
    pack_hilo(x.z, x.w, h1, l1);
    hi[i * 2 + 0] = h0; hi[i * 2 + 1] = h1;
    lo[i * 2 + 0] = l0; lo[i * 2 + 1] = l1;
}

__global__ void trcvt_kernel(const float* __restrict__ src,
                             __nv_bfloat16* __restrict__ dhi, __nv_bfloat16* __restrict__ dlo,
                             int R, int C)
{
    __shared__ float t[32][33];
    const int bz = blockIdx.z;
    const int c0 = blockIdx.x * 32, r0 = blockIdx.y * 32;
    const int tx = threadIdx.x, ty = threadIdx.y;
    const float* s = src + (size_t)bz * R * C;
#pragma unroll
    for (int i = 0; i < 4; i++)
        t[ty + 8 * i][tx] = s[(size_t)(r0 + ty + 8 * i) * C + c0 + tx];
    __syncthreads();
#pragma unroll
    for (int i = 0; i < 4; i++) {
        float v = t[tx][ty + 8 * i];
        __nv_bfloat16 h = __float2bfloat16_rn(v);
        __nv_bfloat16 l = __float2bfloat16_rn(v - __bfloat162float(h));
        size_t o = (size_t)bz * C * R + (size_t)(c0 + ty + 8 * i) * R + r0 + tx;
        dhi[o] = h; dlo[o] = l;
    }
}

// Bias-correction dot products: out[row] = wvec[n] . (hi+lo)[row][0:64]
__global__ __launch_bounds__(256) void cdot_kernel(
    const uint32_t* __restrict__ hi2, const uint32_t* __restrict__ lo2,
    const float* __restrict__ wvec, float* __restrict__ outv, int sel)
{
    __shared__ float w[64];
    const int row = blockIdx.x * 256 + threadIdx.x;
    const int n = (sel == 10) ? ((row >> 10) & 15) : (row >> 11);
    if (threadIdx.x < 64) w[threadIdx.x] = wvec[n * 64 + threadIdx.x];
    __syncthreads();
    float s = 0.f;
    const uint32_t* ph = hi2 + (size_t)row * 32;
    const uint32_t* pl = lo2 + (size_t)row * 32;
#pragma unroll 8
    for (int i = 0; i < 32; i++) {
        uint32_t h = ph[i], l = pl[i];
        __nv_bfloat162 hb = *(__nv_bfloat162*)&h, lb = *(__nv_bfloat162*)&l;
        float v0 = __bfloat162float(hb.x) + __bfloat162float(lb.x);
        float v1 = __bfloat162float(hb.y) + __bfloat162float(lb.y);
        s += v0 * w[i * 2] + v1 * w[i * 2 + 1];
    }
    outv[row] = s;
}

// ---------------------------------------------------------------------------
// HMMA GEMM v2: CTA tile 128x256, warp tile 64x64 (4mt x 4ntp), 8 warps (2x4),
// 2-stage cp.async double buffer.  85 B smem read per MMA -> MMA-bound.
// Stage layout: Ahi 0 (128x80), Alo 10240, Bhi 20480 (256x80), Blo 40960.
// ---------------------------------------------------------------------------
#define STRIDE 80
#define HG_STAGE 61440
#define HG_SMEM  (2 * HG_STAGE)

__global__ __launch_bounds__(256) void hgemm(
    const char* __restrict__ Ahi, const char* __restrict__ Alo,
    const char* __restrict__ Bhi, const char* __restrict__ Blo,
    const float* __restrict__ aux0, const float* __restrict__ aux2,
    float* __restrict__ out0,
    uint32_t* __restrict__ oh0, uint32_t* __restrict__ ol0, int mode)
{
    extern __shared__ char hs[];
    const int tid = threadIdx.x, lane = tid & 31, wid = tid >> 5;
    const int wm = wid >> 2, wn = wid & 3;          // 2 x 4 warps
    const int m0 = blockIdx.y * 128, n0 = blockIdx.x * 256;

    float c[4][8][4] = {};

    const uint32_t sb = smem_u32(hs);
    // A copy coords: 2 threads per row (32B each)
    const int lrowA = tid >> 1, lsegA = (tid & 1) * 32;
    const char* gpAh = Ahi + (size_t)(m0 + lrowA) * KBYTES + lsegA;
    const char* gpAl = Alo + (size_t)(m0 + lrowA) * KBYTES + lsegA;
    const uint32_t dA = sb + lrowA * STRIDE + lsegA;
    // B copy coords: 1 thread per row (64B)
    const char* gpBh = Bhi + (size_t)(n0 + tid) * KBYTES;
    const char* gpBl = Blo + (size_t)(n0 + tid) * KBYTES;
    const uint32_t dB = sb + 20480 + tid * STRIDE;

    // ldmatrix lane offsets
    const int arow_in = (lane & 7) + ((lane >> 3) & 1) * 8;
    const int ak16    = (lane >> 4) * 16;
    const int brow_in = (lane & 7) + (lane >> 4) * 8;
    const int bk16    = ((lane >> 3) & 1) * 16;
    const uint32_t aHiB = sb + (wm * 64 + arow_in) * STRIDE + ak16;
    const uint32_t bHiB = sb + 20480 + (wn * 64 + brow_in) * STRIDE + bk16;

    // prologue: stage 0
    {
        CPA16(dA, gpAh);                 CPA16(dA + 16, gpAh + 16);
        CPA16(dA + 10240, gpAl);         CPA16(dA + 10240 + 16, gpAl + 16);
#pragma unroll
        for (int j = 0; j < 4; j++) {
            CPA16(dB + j * 16, gpBh + j * 16);
            CPA16(dB + 20480 + j * 16, gpBl + j * 16);
        }
        CP_COMMIT();
    }

    for (int ck = 0; ck < 32; ck++) {
        const int st = ck & 1;
        CP_WAIT(0);
        __syncthreads();
        if (ck < 31) {
            const int off = (ck + 1) * 64;
            const uint32_t dA2 = dA + (st ^ 1) * HG_STAGE;
            const uint32_t dB2 = dB + (st ^ 1) * HG_STAGE;
            CPA16(dA2, gpAh + off);             CPA16(dA2 + 16, gpAh + off + 16);
            CPA16(dA2 + 10240, gpAl + off);     CPA16(dA2 + 10240 + 16, gpAl + off + 16);
#pragma unroll
            for (int j = 0; j < 4; j++) {
                CPA16(dB2 + j * 16, gpBh + off + j * 16);
                CPA16(dB2 + 20480 + j * 16, gpBl + off + j * 16);
            }
            CP_COMMIT();
        }

        const uint32_t aH = aHiB + st * HG_STAGE, aL = aH + 10240;
        const uint32_t bH = bHiB + st * HG_STAGE, bL = bH + 20480;
#pragma unroll
        for (int ks = 0; ks < 2; ks++) {
            const int kb = ks * 32;
            uint32_t ah[4][4], al[4][4];
#pragma unroll
            for (int mt = 0; mt < 4; mt++) {
                ldmx4(ah[mt], aH + mt * (16 * STRIDE) + kb);
                ldmx4(al[mt], aL + mt * (16 * STRIDE) + kb);
            }
#pragma unroll
            for (int ntp = 0; ntp < 4; ntp++) {
                uint32_t bh[4], bl[4];
                ldmx4(bh, bH + ntp * (16 * STRIDE) + kb);
                ldmx4(bl, bL + ntp * (16 * STRIDE) + kb);
#pragma unroll
                for (int mt = 0; mt < 4; mt++) {
                    mma16816(c[mt][ntp * 2 + 0], ah[mt], bh + 0);
                    mma16816(c[mt][ntp * 2 + 1], ah[mt], bh + 2);
                    mma16816(c[mt][ntp * 2 + 0], ah[mt], bl + 0);
                    mma16816(c[mt][ntp * 2 + 1], ah[mt], bl + 2);
                    mma16816(c[mt][ntp * 2 + 0], al[mt], bh + 0);
                    mma16816(c[mt][ntp * 2 + 1], al[mt], bh + 2);
                }
            }
        }
    }

    const int g = lane >> 2, tg = lane & 3;
#pragma unroll
    for (int mt = 0; mt < 4; mt++) {
#pragma unroll
        for (int half = 0; half < 2; half++) {
            const int m = m0 + wm * 64 + mt * 16 + g + half * 8;
#pragma unroll
            for (int nt = 0; nt < 8; nt++) {
                float v0 = c[mt][nt][half * 2 + 0];
                float v1 = c[mt][nt][half * 2 + 1];
                const int coln = n0 + wn * 64 + nt * 8 + tg * 2;
                if (mode == 3) {
                    size_t o = (size_t)m * DD + coln;
                    float2 res = *(const float2*)(aux2 + o);
                    *(float2*)(out0 + o) =
                        make_float2(v0 + aux0[coln] + res.x, v1 + aux0[coln + 1] + res.y);
                } else if (mode == 4) {
                    int hd = coln >> 6, h = coln & 63;
                    size_t o = ((size_t)hd * RR + m) * HH + h;
                    uint32_t hi, lo;
                    pack_hilo(v0, v1, hi, lo);
                    oh0[o >> 1] = hi; ol0[o >> 1] = lo;
                } else {
                    int hd = coln >> 6, h = coln & 63;
                    int b = m >> 10, l = m & 1023;
                    size_t o = ((size_t)(b * NH + hd) * LL + l) * HH + h;
                    float b0 = aux0 ? aux0[coln] : 0.f;
                    float b1 = aux0 ? aux0[coln + 1] : 0.f;
                    uint32_t hi, lo;
                    pack_hilo(v0 + b0, v1 + b1, hi, lo);
                    oh0[o >> 1] = hi; ol0[o >> 1] = lo;
                }
            }
        }
    }
}

// ---------------------------------------------------------------------------
// HMMA flash attention (unchanged from R10): 128 q-rows per CTA, 192-row
// rolling R ring, per-warp 5-tile band trim, c1/c2 bias-correction.
// ---------------------------------------------------------------------------
#define AST     144
#define POSW2   84
#define OFF_KH  0
#define OFF_KL  9216
#define OFF_VH  18432
#define OFF_VL  27648
#define OFF_RH  36864
#define OFF_RL  64512
#define OFF_POS 92160
#define OFF_CC  135168
#define OFF_C2  135424
#define ATTN_BYTES 136192
#define SCALE2F (0.125f * LOG2E)

__global__ __launch_bounds__(256) void attn2(const int* __restrict__ pad,
    const float* __restrict__ c1g, const float* __restrict__ c2g,
    const uint32_t* __restrict__ qhh, const uint32_t* __restrict__ qhl,
    const uint32_t* __restrict__ khh, const uint32_t* __restrict__ khl,
    const uint32_t* __restrict__ vhh, const uint32_t* __restrict__ vhl,
    const uint32_t* __restrict__ rph, const uint32_t* __restrict__ rpl,
    uint32_t* __restrict__ outh, uint32_t* __restrict__ outl)
{
    extern __shared__ char dyn[];
    float* pos = (float*)(dyn + OFF_POS);
    float* cc  = (float*)(dyn + OFF_CC);
    float* c2s = (float*)(dyn + OFF_C2);

    const int tid = threadIdx.x, lane = tid & 31, w = tid >> 5;
    const int g = lane >> 2, tg = lane & 3;
    const int bn = blockIdx.y, b = bn >> 4, n = bn & 15;
    const int l0 = blockIdx.x * 128;

    const uint32_t uD  = smem_u32(dyn);
    const uint32_t uKH = uD + OFF_KH, uKL = uD + OFF_KL;
    const uint32_t uVH = uD + OFF_VH, uVL = uD + OFF_VL;
    const uint32_t uRH = uD + OFF_RH, uRL = uD + OFF_RL;

    const int arow = (lane & 7) + ((lane >> 3) & 1) * 8;
    const int ak16 = (lane >> 4) * 16;
    const int brow = (lane & 7) + (lane >> 4) * 8;
    const int bk16 = ((lane >> 3) & 1) * 16;
    const int vrow = (lane & 7) + ((lane >> 3) & 1) * 8;
    const int vsel = (lane >> 4) * 16;

    {
        const int lrowQ = tid >> 1, lsegQ = (tid & 1) * 64;
        const size_t qoff = ((size_t)(bn * LL + l0 + lrowQ) << 7) + lsegQ;
        const int dst = lrowQ * AST + lsegQ;
        const uint4* s = (const uint4*)((const char*)qhh + qoff);
        uint4* d = (uint4*)(dyn + OFF_RH + dst);
        d[0] = s[0]; d[1] = s[1]; d[2] = s[2]; d[3] = s[3];
        s = (const uint4*)((const char*)qhl + qoff);
        d = (uint4*)(dyn + OFF_RL + dst);
        d[0] = s[0]; d[1] = s[1]; d[2] = s[2]; d[3] = s[3];
    }
    __syncthreads();
    uint32_t fqh[4][4], fql[4][4];
    {
        const uint32_t aoh = uRH + (w * 16 + arow) * AST + ak16;
        const uint32_t aol = uRL + (w * 16 + arow) * AST + ak16;
#pragma unroll
        for (int ks = 0; ks < 4; ks++) {
            ldmx4(fqh[ks], aoh + ks * 32);
            ldmx4(fql[ks], aol + ks * 32);
        }
    }

    float o[8][4] = {};
    float mrow[2] = {-INFINITY, -INFINITY};
    float lrowv[2] = {0.f, 0.f};

    for (int kt = 0; kt < LL / 64; kt++) {
        const int m0 = kt * 64;
        const int rel0 = LL + m0 - l0 - 127;
        const int roff = (kt % 3) * 64;

        __syncthreads();
        {
            const int lrow4 = tid >> 2, lseg4 = (tid & 3) * 32;
            const size_t kv = ((size_t)(bn * LL + m0 + lrow4) << 7) + lseg4;
            const uint32_t dr = uD + lrow4 * AST + lseg4;
            const char* s;
#define KCP(buf, at) \
            s = (const char*)(buf) + kv; \
            CPA16(dr + (at), s); CPA16(dr + (at) + 16, s + 16);
            KCP(khh, OFF_KH) KCP(khl, OFF_KL) KCP(vhh, OFF_VH) KCP(vhl, OFF_VL)
#undef KCP
            if (kt == 0) {
#pragma unroll
                for (int cch = 0; cch < 3; cch++) {
                    const int rowl = cch * 64 + lrow4;
                    int rel = rel0 + rowl;
                    rel = rel < 0 ? 0 : (rel > RR - 1 ? RR - 1 : rel);
                    const char* rs = (const char*)rph + (((size_t)(n * RR + rel)) << 7) + lseg4;
                    uint32_t rd = uRH + rowl * AST + lseg4;
                    CPA16(rd, rs); CPA16(rd + 16, rs + 16);
                    rs = (const char*)rpl + (((size_t)(n * RR + rel)) << 7) + lseg4;
                    rd = uRL + rowl * AST + lseg4;
                    CPA16(rd, rs); CPA16(rd + 16, rs + 16);
                }
            } else {
                int rel = rel0 + 128 + lrow4;
                rel = rel < 0 ? 0 : (rel > RR - 1 ? RR - 1 : rel);
                const int base2 = (128 + roff) % 192;
                const int phys = base2 + lrow4;
                const char* rs = (const char*)rph + (((size_t)(n * RR + rel)) << 7) + lseg4;
                uint32_t rd = uRH + phys * AST + lseg4;
                CPA16(rd, rs); CPA16(rd + 16, rs + 16);
                rs = (const char*)rpl + (((size_t)(n * RR + rel)) << 7) + lseg4;
                rd = uRL + phys * AST + lseg4;
                CPA16(rd, rs); CPA16(rd + 16, rs + 16);
            }
            CP_COMMIT();
            if (tid < 64)
                cc[tid] = c1g[(size_t)bn * LL + m0 + tid] * SCALE2F +
                          (pad[b * LL + m0 + tid] ? (-1.0e6f * LOG2E) : 0.0f);
            if (tid < 192) {
                int rel = rel0 + tid;
                rel = rel < 0 ? 0 : (rel > RR - 1 ? RR - 1 : rel);
                c2s[tid] = c2g[n * RR + rel];
            }
        }
        CP_WAIT(0);
        __syncthreads();

#pragma unroll
        for (int npi = 0; npi < 5; npi++) {
            const int np = npi + 7 - w;
            float b0[4] = {}, b1[4] = {};
            int pr16 = np * 16 + roff;
            if (pr16 >= 192) pr16 -= 192;
            const uint32_t rbase = (pr16 + brow) * AST + bk16;
#pragma unroll
            for (int ks = 0; ks < 4; ks++) {
                uint32_t bh[4], bl[4];
                const uint32_t ro = rbase + ks * 32;
                ldmx4(bh, uRH + ro);
                ldmx4(bl, uRL + ro);
                mma16816(b0, fqh[ks], bh + 0);
                mma16816(b1, fqh[ks], bh + 2);
                mma16816(b0, fqh[ks], bl + 0);
                mma16816(b1, fqh[ks], bl + 2);
                mma16816(b0, fql[ks], bh + 0);
                mma16816(b1, fql[ks], bh + 2);
            }
            const int pc   = npi * 16 + tg * 2;
            const int cidx = np * 16 + tg * 2;
            float* pr0 = pos + (w * 16 + g) * POSW2;
            float* pr1 = pos + (w * 16 + g + 8) * POSW2;
            const float ca = c2s[cidx],     cb = c2s[cidx + 1];
            const float cd = c2s[cidx + 8], ce = c2s[cidx + 9];
            *(float2*)(pr0 + pc)     = make_float2(b0[0] + ca, b0[1] + cb);
            *(float2*)(pr1 + pc)     = make_float2(b0[2] + ca, b0[3] + cb);
            *(float2*)(pr0 + pc + 8) = make_float2(b1[0] + cd, b1[1] + ce);
            *(float2*)(pr1 + pc + 8) = make_float2(b1[2] + cd, b1[3] + ce);
        }

        float sfr[8][4] = {};
#pragma unroll
        for (int ks = 0; ks < 4; ks++) {
#pragma unroll
            for (int np = 0; np < 4; np++) {
                uint32_t bh[4], bl[4];
                const uint32_t ro = (np * 16 + brow) * AST + bk16 + ks * 32;
                ldmx4(bh, uKH + ro);
                ldmx4(bl, uKL + ro);
                mma16816(sfr[np * 2 + 0], fqh[ks], bh + 0);
                mma16816(sfr[np * 2 + 1], fqh[ks], bh + 2);
                mma16816(sfr[np * 2 + 0], fqh[ks], bl + 0);
                mma16816(sfr[np * 2 + 1], fqh[ks], bl + 2);
                mma16816(sfr[np * 2 + 0], fql[ks], bh + 0);
                mma16816(sfr[np * 2 + 1], fql[ks], bh + 2);
            }
        }
        __syncwarp();

#pragma unroll
        for (int r2 = 0; r2 < 2; r2++) {
            const int ii = g + r2 * 8;
            const float* pr = pos + (w * 16 + ii) * POSW2 + (15 - ii);
            float mx = -INFINITY;
#pragma unroll
            for (int nt = 0; nt < 8; nt++) {
#pragma unroll
                for (int v2 = 0; v2 < 2; v2++) {
                    const int j = nt * 8 + tg * 2 + v2;
                    float t = fmaf(sfr[nt][r2 * 2 + v2] + pr[j], SCALE2F, cc[j]);
                    sfr[nt][r2 * 2 + v2] = t;
                    mx = fmaxf(mx, t);
                }
            }
            mx = fmaxf(mx, __shfl_xor_sync(0xffffffffu, mx, 1));
            mx = fmaxf(mx, __shfl_xor_sync(0xffffffffu, mx, 2));
            const float mnew = fmaxf(mrow[r2], mx);
            const float alpha = exp2p(mrow[r2] - mnew);
            mrow[r2] = mnew;
            float ssum = 0.f;
#pragma unroll
            for (int nt = 0; nt < 8; nt++) {
#pragma unroll
                for (int v2 = 0; v2 < 2; v2++) {
                    float p = exp2p(sfr[nt][r2 * 2 + v2] - mnew);
                    sfr[nt][r2 * 2 + v2] = p;
                    ssum += p;
                }
            }
            ssum += __shfl_xor_sync(0xffffffffu, ssum, 1);
            ssum += __shfl_xor_sync(0xffffffffu, ssum, 2);
            lrowv[r2] = lrowv[r2] * alpha + ssum;
#pragma unroll
            for (int ht = 0; ht < 8; ht++) {
                o[ht][r2 * 2 + 0] *= alpha;
                o[ht][r2 * 2 + 1] *= alpha;
            }
        }

#pragma unroll
        for (int ks = 0; ks < 4; ks++) {
            uint32_t aph[4], apl[4];
#pragma unroll
            for (int q2 = 0; q2 < 2; q2++) {
                const float* f = sfr[2 * ks + q2];
                __nv_bfloat16 h0 = __float2bfloat16_rn(f[0]);
                __nv_bfloat16 h1 = __float2bfloat16_rn(f[1]);
                __nv_bfloat16 h2 = __float2bfloat16_rn(f[2]);
                __nv_bfloat16 h3 = __float2bfloat16_rn(f[3]);
                __nv_bfloat162 t;
                t.x = h0; t.y = h1; aph[q2 * 2 + 0] = *(uint32_t*)&t;
                t.x = h2; t.y = h3; aph[q2 * 2 + 1] = *(uint32_t*)&t;
                apl[q2 * 2 + 0] = pack_bf2(f[0] - __bfloat162float(h0),
                                           f[1] - __bfloat162float(h1));
                apl[q2 * 2 + 1] = pack_bf2(f[2] - __bfloat162float(h2),
                                           f[3] - __bfloat162float(h3));
            }
            const uint32_t vo = (ks * 16 + vrow) * AST + vsel;
#pragma unroll
            for (int hp = 0; hp < 4; hp++) {
                uint32_t vbh[4], vbl[4];
                ldmx4t(vbh, uVH + vo + hp * 32);
                ldmx4t(vbl, uVL + vo + hp * 32);
                mma16816(o[hp * 2 + 0], aph, vbh + 0);
                mma16816(o[hp * 2 + 1], aph, vbh + 2);
                mma16816(o[hp * 2 + 0], aph, vbl + 0);
                mma16816(o[hp * 2 + 1], aph, vbl + 2);
                mma16816(o[hp * 2 + 0], apl, vbh + 0);
                mma16816(o[hp * 2 + 1], apl, vbh + 2);
            }
        }
    }

#pragma unroll
    for (int r2 = 0; r2 < 2; r2++) {
        const int i = w * 16 + g + r2 * 8;
        const int rowg = b * LL + l0 + i;
        const float inv = 1.0f / lrowv[r2];
#pragma unroll
        for (int ht = 0; ht < 8; ht++) {
            float v0 = o[ht][r2 * 2 + 0] * inv;
            float v1 = o[ht][r2 * 2 + 1] * inv;
            const int col = n * 64 + ht * 8 + tg * 2;
            uint32_t hi, lo;
            pack_hilo(v0, v1, hi, lo);
            outh[(size_t)rowg * 512 + (col >> 1)] = hi;
            outl[(size_t)rowg * 512 + (col >> 1)] = lo;
        }
    }
}

// ---------------------------------------------------------------------------
// LayerNorm
// ---------------------------------------------------------------------------
__global__ __launch_bounds__(256) void ln_kernel(
    float* __restrict__ X, const float* __restrict__ g, const float* __restrict__ bta)
{
    __shared__ float red[8];
    const int row = blockIdx.x;
    const int t   = threadIdx.x;
    float4 x = *(float4*)(X + (size_t)row * DD + t * 4);

    float s = x.x + x.y + x.z + x.w;
#pragma unroll
    for (int d = 16; d; d >>= 1) s += __shfl_xor_sync(0xffffffffu, s, d);
    if ((t & 31) == 0) red[t >> 5] = s;
    __syncthreads();
    float tot = red[0] + red[1] + red[2] + red[3] + red[4] + red[5] + red[6] + red[7];
    float mu = tot * (1.0f / DD);
    __syncthreads();

    float dx0 = x.x - mu, dx1 = x.y - mu, dx2 = x.z - mu, dx3 = x.w - mu;
    float sq = dx0 * dx0 + dx1 * dx1 + dx2 * dx2 + dx3 * dx3;
#pragma unroll
    for (int d = 16; d; d >>= 1) sq += __shfl_xor_sync(0xffffffffu, sq, d);
    if ((t & 31) == 0) red[t >> 5] = sq;
    __syncthreads();
    float var = (red[0] + red[1] + red[2] + red[3] + red[4] + red[5] + red[6] + red[7]) * (1.0f / DD);
    float rs = rsqrtf(var + 1e-5f);

    float4 gg = *(const float4*)(g + t * 4);
    float4 bb = *(const float4*)(bta + t * 4);
    float4 y = make_float4(dx0 * rs * gg.x + bb.x, dx1 * rs * gg.y + bb.y,
                           dx2 * rs * gg.z + bb.z, dx3 * rs * gg.w + bb.w);
    *(float4*)(X + (size_t)row * DD + t * 4) = y;
}

// ---------------------------------------------------------------------------
// Launch
// ---------------------------------------------------------------------------
extern "C" void kernel_launch(void* const* d_in, const int* in_sizes, int n_in,
                              void* d_out, int out_size)
{
    const float* q   = (const float*)d_in[0];
    const float* k   = (const float*)d_in[1];
    const float* v   = (const float*)d_in[2];
    const float* pe  = (const float*)d_in[3];
    const int*   pad = (const int*)d_in[4];
    const float* q_w = (const float*)d_in[5];
    const float* k_w = (const float*)d_in[6];
    const float* k_b = (const float*)d_in[7];
    const float* v_w = (const float*)d_in[8];
    const float* v_b = (const float*)d_in[9];
    const float* rwb = (const float*)d_in[10];
    const float* rrb = (const float*)d_in[11];
    const float* r_k = (const float*)d_in[12];
    const float* pw  = (const float*)d_in[13];
    const float* pb  = (const float*)d_in[14];
    const float* lg  = (const float*)d_in[15];
    const float* lb  = (const float*)d_in[16];
    float* out = (float*)d_out;

    cudaFuncSetAttribute(attn2, cudaFuncAttributeMaxDynamicSharedMemorySize, ATTN_BYTES);
    cudaFuncSetAttribute(hgemm, cudaFuncAttributeMaxDynamicSharedMemorySize, HG_SMEM);

    char *inhi, *inlo, *wthi, *wtlo;
    cudaGetSymbolAddress((void**)&inhi, g_INhi4);
    cudaGetSymbolAddress((void**)&inlo, g_INlo4);
    cudaGetSymbolAddress((void**)&wthi, g_WThi4);
    cudaGetSymbolAddress((void**)&wtlo, g_WTlo4);
    uint32_t *qhh, *qhl, *khh, *khl, *vhh, *vhl, *rph, *rpl;
    float *c1p, *c2p;
    cudaGetSymbolAddress((void**)&qhh, g_QHh2);
    cudaGetSymbolAddress((void**)&qhl, g_QHl2);
    cudaGetSymbolAddress((void**)&khh, g_KHh2);
    cudaGetSymbolAddress((void**)&khl, g_KHl2);
    cudaGetSymbolAddress((void**)&vhh, g_VHh2);
    cudaGetSymbolAddress((void**)&vhl, g_VHl2);
    cudaGetSymbolAddress((void**)&rph, g_RPh2);
    cudaGetSymbolAddress((void**)&rpl, g_RPl2);
    cudaGetSymbolAddress((void**)&c1p, g_C1);
    cudaGetSymbolAddress((void**)&c2p, g_C2);

    dim3 gg(4, 32);            // N=1024/256, M=4096/128
    dim3 tr(32, 8);
    const int n4_in = BB * LL * DD / 4;

    // ---- q projection -> qh bf16 hi/lo (no bias) ----
    cvt_kernel<<<(n4_in + 255) / 256, 256>>>((const float4*)q, (uint32_t*)inhi, (uint32_t*)inlo, n4_in);
    trcvt_kernel<<<dim3(32, 32, 1), tr>>>(q_w, (__nv_bfloat16*)wthi, (__nv_bfloat16*)wtlo, DD, DD);
    hgemm<<<gg, 256, HG_SMEM>>>(inhi, inlo, wthi, wtlo, nullptr, nullptr, nullptr, qhh, qhl, 1);
    // ---- k projection (+k_b) ----
    cvt_kernel<<<(n4_in + 255) / 256, 256>>>((const float4*)k, (uint32_t*)inhi, (uint32_t*)inlo, n4_in);
    trcvt_kernel<<<dim3(32, 32, 1), tr>>>(k_w, (__nv_bfloat16*)wthi, (__nv_bfloat16*)wtlo, DD, DD);
    hgemm<<<gg, 256, HG_SMEM>>>(inhi, inlo, wthi, wtlo, k_b, nullptr, nullptr, khh, khl, 1);
    cdot_kernel<<<BB * NH * LL / 256, 256>>>(khh, khl, rwb, c1p, 10);
    // ---- v projection (+v_b) ----
    cvt_kernel<<<(n4_in + 255) / 256, 256>>>((const float4*)v, (uint32_t*)inhi, (uint32_t*)inlo, n4_in);
    trcvt_kernel<<<dim3(32, 32, 1), tr>>>(v_w, (__nv_bfloat16*)wthi, (__nv_bfloat16*)wtlo, DD, DD);
    hgemm<<<gg, 256, HG_SMEM>>>(inhi, inlo, wthi, wtlo, v_b, nullptr, nullptr, vhh, vhl, 2);
    // ---- rp projection ----
    const int n4_pe = RR * DD / 4;
    cvt_kernel<<<(n4_pe + 255) / 256, 256>>>((const float4*)pe, (uint32_t*)inhi, (uint32_t*)inlo, n4_pe);
    trcvt_kernel<<<dim3(2, 32, 16), tr>>>(r_k, (__nv_bfloat16*)wthi, (__nv_bfloat16*)wtlo, DD, HH);
    hgemm<<<dim3(4, 16), 256, HG_SMEM>>>(inhi, inlo, wthi, wtlo, nullptr, nullptr, nullptr, rph, rpl, 4);
    cdot_kernel<<<NH * RR / 256, 256>>>(rph, rpl, rrb, c2p, 11);
    // ---- attention (128 q-rows per CTA) ----
    attn2<<<dim3(LL / 128, BB * NH), 256, ATTN_BYTES>>>(pad, c1p, c2p, qhh, qhl,
                                                        khh, khl, vhh, vhl, rph, rpl,
                                                        (uint32_t*)inhi, (uint32_t*)inlo);
    // ---- post projection + residual ----
    trcvt_kernel<<<dim3(32, 32, 1), tr>>>(pw, (__nv_bfloat16*)wthi, (__nv_bfloat16*)wtlo, DD, DD);
    hgemm<<<gg, 256, HG_SMEM>>>(inhi, inlo, wthi, wtlo, pb, q, out, nullptr, nullptr, 3);
    // ---- layernorm ----
    ln_kernel<<<BB * LL, 256>>>(out, lg, lb);
}

// round 12
// speedup vs baseline: 3.2625x; 3.2625x over previous
#include <cuda_runtime.h>
#include <cuda_fp16.h>
#include <math.h>
#include <stdint.h>

// Problem constants
#define BB   4
#define LL   1024
#define DD   1024
#define NH   16
#define HH   64
#define RR   2048
#define LOG2E 1.4426950408889634f
#define KBYTES 2048        // K=1024 fp16 row stride in bytes

// ---------------------------------------------------------------------------
// Device scratch (fp16 everywhere, packed as uint32 = half2)
// ---------------------------------------------------------------------------
__device__ uint4 g_IN4[BB * LL * DD / 8];     // 8 MB fp16 activations
__device__ uint4 g_WT4[DD * DD / 8];          // 2 MB fp16 weights, [n][k]

__device__ uint32_t g_QH2[BB * NH * LL * HH / 2];    // qh
__device__ uint32_t g_KH2[BB * NH * LL * HH / 2];
__device__ uint32_t g_VH2[BB * NH * LL * HH / 2];
__device__ uint32_t g_RP2[NH * RR * HH / 2];
__device__ float    g_C1[BB * NH * LL];              // r_w_bias . kh
__device__ float    g_C2[NH * RR];                   // r_r_bias . r

__device__ __forceinline__ uint32_t smem_u32(const void* p) {
    uint32_t a;
    asm("{ .reg .u64 t; cvta.to.shared.u64 t, %1; cvt.u32.u64 %0, t; }" : "=r"(a) : "l"(p));
    return a;
}
__device__ __forceinline__ void ldmx4(uint32_t* r, uint32_t addr) {
    asm volatile("ldmatrix.sync.aligned.m8n8.x4.shared.b16 {%0,%1,%2,%3}, [%4];"
        : "=r"(r[0]), "=r"(r[1]), "=r"(r[2]), "=r"(r[3]) : "r"(addr));
}
__device__ __forceinline__ void ldmx4t(uint32_t* r, uint32_t addr) {
    asm volatile("ldmatrix.sync.aligned.m8n8.x4.trans.shared.b16 {%0,%1,%2,%3}, [%4];"
        : "=r"(r[0]), "=r"(r[1]), "=r"(r[2]), "=r"(r[3]) : "r"(addr));
}
__device__ __forceinline__ void mma16816(float* c, const uint32_t* a, const uint32_t* b) {
    asm volatile("mma.sync.aligned.m16n8k16.row.col.f32.f16.f16.f32 "
        "{%0,%1,%2,%3}, {%4,%5,%6,%7}, {%8,%9}, {%0,%1,%2,%3};"
        : "+f"(c[0]), "+f"(c[1]), "+f"(c[2]), "+f"(c[3])
        : "r"(a[0]), "r"(a[1]), "r"(a[2]), "r"(a[3]), "r"(b[0]), "r"(b[1]));
}
#define CPA16(dst, src) \
    asm volatile("cp.async.cg.shared.global [%0], [%1], 16;" :: "r"(dst), "l"(src) : "memory")
#define CP_COMMIT() asm volatile("cp.async.commit_group;" ::: "memory")
#define CP_WAIT(n)  asm volatile("cp.async.wait_group %0;" :: "n"(n) : "memory")

__device__ __forceinline__ uint32_t pack_h2(float a, float b) {
    __half2 h2; h2.x = __float2half_rn(a); h2.y = __float2half_rn(b);
    return *(uint32_t*)&h2;
}
// exp2 on FMA pipe: deg-5 poly + exponent splice.  arg <= 0, clamped at -125.
__device__ __forceinline__ float exp2p(float t) {
    t = fmaxf(t, -125.0f);
    float tr = t + 12582912.0f;
    int   n  = __float_as_int(tr) - 0x4B400000;
    float f  = t - (tr - 12582912.0f);
    float p  = 1.3333558146e-3f;
    p = fmaf(p, f, 9.6181291076e-3f);
    p = fmaf(p, f, 5.5504108665e-2f);
    p = fmaf(p, f, 2.4022650696e-1f);
    p = fmaf(p, f, 6.9314718056e-1f);
    p = fmaf(p, f, 1.0f);
    return __int_as_float(__float_as_int(p) + (n << 23));
}

// ---------------------------------------------------------------------------
// Prepasses
// ---------------------------------------------------------------------------
__global__ __launch_bounds__(256) void cvt_kernel(const float4* __restrict__ src,
                                                  uint32_t* __restrict__ dst, int n4)
{
    int i = blockIdx.x * 256 + threadIdx.x;
    if (i >= n4) return;
    float4 x = src[i];
    dst[i * 2 + 0] = pack_h2(x.x, x.y);
    dst[i * 2 + 1] = pack_h2(x.z, x.w);
}

__global__ void trcvt_kernel(const float* __restrict__ src,
                             __half* __restrict__ dstv, int R, int C)
{
    __shared__ float t[32][33];
    const int bz = blockIdx.z;
    const int c0 = blockIdx.x * 32, r0 = blockIdx.y * 32;
    const int tx = threadIdx.x, ty = threadIdx.y;
    const float* s = src + (size_t)bz * R * C;
#pragma unroll
    for (int i = 0; i < 4; i++)
        t[ty + 8 * i][tx] = s[(size_t)(r0 + ty + 8 * i) * C + c0 + tx];
    __syncthreads();
#pragma unroll
    for (int i = 0; i < 4; i++) {
        float v = t[tx][ty + 8 * i];
        size_t o = (size_t)bz * C * R + (size_t)(c0 + ty + 8 * i) * R + r0 + tx;
        dstv[o] = __float2half_rn(v);
    }
}

// Bias-correction dot products: out[row] = wvec[n] . x[row][0:64]
__global__ __launch_bounds__(256) void cdot_kernel(
    const uint32_t* __restrict__ x2, const float* __restrict__ wvec,
    float* __restrict__ outv, int sel)
{
    __shared__ float w[64];
    const int row = blockIdx.x * 256 + threadIdx.x;
    const int n = (sel == 10) ? ((row >> 10) & 15) : (row >> 11);
    if (threadIdx.x < 64) w[threadIdx.x] = wvec[n * 64 + threadIdx.x];
    __syncthreads();
    float s = 0.f;
    const uint32_t* ph = x2 + (size_t)row * 32;
#pragma unroll 8
    for (int i = 0; i < 32; i++) {
        uint32_t h = ph[i];
        __half2 hb = *(__half2*)&h;
        s += __half2float(hb.x) * w[i * 2] + __half2float(hb.y) * w[i * 2 + 1];
    }
    outv[row] = s;
}

// ---------------------------------------------------------------------------
// HMMA GEMM fp16 single-term (R10 structure: sync LDG + register prefetch)
// mode 1/2: oh0(+aux0 if non-null), bnlh half2 pairs
// mode 3: fp32 out0 = D + aux0[col] + aux2[m*D+col]
// mode 4: oh0, rp layout [n][r][h] half2 pairs
// ---------------------------------------------------------------------------
#define STRIDE 80

__global__ __launch_bounds__(256) void hgemm(
    const char* __restrict__ Am, const char* __restrict__ Bm,
    const float* __restrict__ aux0, const float* __restrict__ aux2,
    float* __restrict__ out0, uint32_t* __restrict__ oh0, int mode)
{
    __shared__ char sA[128 * STRIDE];
    __shared__ char sB[128 * STRIDE];

    const int tid = threadIdx.x, lane = tid & 31, wid = tid >> 5;
    const int wm = wid >> 1, wn = wid & 1;
    const int m0 = blockIdx.y * 128, n0 = blockIdx.x * 128;

    float c[2][8][4] = {};

    const int lrow = tid >> 1, lseg = (tid & 1) * 32;
    const char* gpA = Am + (size_t)(m0 + lrow) * KBYTES + lseg;
    const char* gpB = Bm + (size_t)(n0 + lrow) * KBYTES + lseg;
    const int srow = lrow * STRIDE + lseg;
    char* spA = sA + srow;
    char* spB = sB + srow;

    const uint32_t aBase = smem_u32(sA);
    const uint32_t bBase = smem_u32(sB);
    const int arow_in = (lane & 7) + ((lane >> 3) & 1) * 8;
    const int ak16    = (lane >> 4) * 16;
    const int brow_in = (lane & 7) + (lane >> 4) * 8;
    const int bk16    = ((lane >> 3) & 1) * 16;
    const uint32_t aOff = aBase + (wm * 32 + arow_in) * STRIDE + ak16;
    const uint32_t bOff = bBase + (wn * 64 + brow_in) * STRIDE + bk16;

    uint4 pfa0, pfa1, pfb0, pfb1;
    pfa0 = *(const uint4*)(gpA);  pfa1 = *(const uint4*)(gpA + 16);
    pfb0 = *(const uint4*)(gpB);  pfb1 = *(const uint4*)(gpB + 16);

    for (int ck = 0; ck < 32; ck++) {
        *(uint4*)(spA) = pfa0; *(uint4*)(spA + 16) = pfa1;
        *(uint4*)(spB) = pfb0; *(uint4*)(spB + 16) = pfb1;
        __syncthreads();
        if (ck < 31) {
            int off = (ck + 1) * 64;
            pfa0 = *(const uint4*)(gpA + off); pfa1 = *(const uint4*)(gpA + off + 16);
            pfb0 = *(const uint4*)(gpB + off); pfb1 = *(const uint4*)(gpB + off + 16);
        }
#pragma unroll
        for (int ks = 0; ks < 2; ks++) {
            const int kb = ks * 32;
            uint32_t ah[2][4];
#pragma unroll
            for (int mt = 0; mt < 2; mt++)
                ldmx4(ah[mt], aOff + mt * (16 * STRIDE) + kb);
#pragma unroll
            for (int ntp = 0; ntp < 4; ntp++) {
                uint32_t bh[4];
                ldmx4(bh, bOff + ntp * (16 * STRIDE) + kb);
#pragma unroll
                for (int mt = 0; mt < 2; mt++) {
                    mma16816(c[mt][ntp * 2 + 0], ah[mt], bh + 0);
                    mma16816(c[mt][ntp * 2 + 1], ah[mt], bh + 2);
                }
            }
        }
        __syncthreads();
    }

    const int g = lane >> 2, tg = lane & 3;
#pragma unroll
    for (int mt = 0; mt < 2; mt++) {
#pragma unroll
        for (int half = 0; half < 2; half++) {
            const int m = m0 + wm * 32 + mt * 16 + g + half * 8;
#pragma unroll
            for (int nt = 0; nt < 8; nt++) {
                float v0 = c[mt][nt][half * 2 + 0];
                float v1 = c[mt][nt][half * 2 + 1];
                const int coln = n0 + wn * 64 + nt * 8 + tg * 2;
                if (mode == 3) {
                    size_t o = (size_t)m * DD + coln;
                    float2 res = *(const float2*)(aux2 + o);
                    *(float2*)(out0 + o) =
                        make_float2(v0 + aux0[coln] + res.x, v1 + aux0[coln + 1] + res.y);
                } else if (mode == 4) {
                    int hd = coln >> 6, h = coln & 63;
                    size_t o = ((size_t)hd * RR + m) * HH + h;
                    oh0[o >> 1] = pack_h2(v0, v1);
                } else {
                    int hd = coln >> 6, h = coln & 63;
                    int b = m >> 10, l = m & 1023;
                    size_t o = ((size_t)(b * NH + hd) * LL + l) * HH + h;
                    float b0 = aux0 ? aux0[coln] : 0.f;
                    float b1 = aux0 ? aux0[coln + 1] : 0.f;
                    oh0[o >> 1] = pack_h2(v0 + b0, v1 + b1);
                }
            }
        }
    }
}

// ---------------------------------------------------------------------------
// HMMA flash attention, fp16 single-term: 128 q-rows per CTA (256 thr, 8 warps),
// 192-row rolling R ring, per-warp 5-tile band trim, c1/c2 scalars.
// smem ~88KB -> 2 CTA/SM.
// ---------------------------------------------------------------------------
#define AST     144
#define POSW2   84
#define OFF_K   0
#define OFF_V   9216
#define OFF_R   18432
#define OFF_POS 46080
#define OFF_CC  89088
#define OFF_C2  89344
#define ATTN_BYTES 90112
#define SCALE2F (0.125f * LOG2E)

__global__ __launch_bounds__(256) void attn2(const int* __restrict__ pad,
    const float* __restrict__ c1g, const float* __restrict__ c2g,
    const uint32_t* __restrict__ qh2, const uint32_t* __restrict__ kh2,
    const uint32_t* __restrict__ vh2, const uint32_t* __restrict__ rp2,
    uint32_t* __restrict__ outp)
{
    extern __shared__ char dyn[];
    float* pos = (float*)(dyn + OFF_POS);
    float* cc  = (float*)(dyn + OFF_CC);
    float* c2s = (float*)(dyn + OFF_C2);

    const int tid = threadIdx.x, lane = tid & 31, w = tid >> 5;
    const int g = lane >> 2, tg = lane & 3;
    const int bn = blockIdx.y, b = bn >> 4, n = bn & 15;
    const int l0 = blockIdx.x * 128;

    const uint32_t uD = smem_u32(dyn);
    const uint32_t uK = uD + OFF_K, uV = uD + OFF_V, uR = uD + OFF_R;

    const int arow = (lane & 7) + ((lane >> 3) & 1) * 8;
    const int ak16 = (lane >> 4) * 16;
    const int brow = (lane & 7) + (lane >> 4) * 8;
    const int bk16 = ((lane >> 3) & 1) * 16;
    const int vrow = (lane & 7) + ((lane >> 3) & 1) * 8;
    const int vsel = (lane >> 4) * 16;

    // ---- Prologue: stage qh (128 rows) in R region, extract A-frags ----
    {
        const int lrowQ = tid >> 1, lsegQ = (tid & 1) * 64;
        const size_t qoff = ((size_t)(bn * LL + l0 + lrowQ) << 7) + lsegQ;
        const uint4* s = (const uint4*)((const char*)qh2 + qoff);
        uint4* d = (uint4*)(dyn + OFF_R + lrowQ * AST + lsegQ);
        d[0] = s[0]; d[1] = s[1]; d[2] = s[2]; d[3] = s[3];
    }
    __syncthreads();
    uint32_t fqh[4][4];
    {
        const uint32_t ao = uR + (w * 16 + arow) * AST + ak16;
#pragma unroll
        for (int ks = 0; ks < 4; ks++)
            ldmx4(fqh[ks], ao + ks * 32);
    }

    float o[8][4] = {};
    float mrow[2] = {-INFINITY, -INFINITY};
    float lrowv[2] = {0.f, 0.f};

    for (int kt = 0; kt < LL / 64; kt++) {
        const int m0 = kt * 64;
        const int rel0 = LL + m0 - l0 - 127;
        const int roff = (kt % 3) * 64;

        __syncthreads();
        // ---- async loads: K/V (64 rows) + R ring (64 or 192 rows) ----
        {
            const int lrow4 = tid >> 2, lseg4 = (tid & 3) * 32;
            const size_t kv = ((size_t)(bn * LL + m0 + lrow4) << 7) + lseg4;
            const uint32_t dr = uD + lrow4 * AST + lseg4;
            const char* s;
            s = (const char*)kh2 + kv;
            CPA16(dr + OFF_K, s); CPA16(dr + OFF_K + 16, s + 16);
            s = (const char*)vh2 + kv;
            CPA16(dr + OFF_V, s); CPA16(dr + OFF_V + 16, s + 16);
            if (kt == 0) {
#pragma unroll
                for (int cch = 0; cch < 3; cch++) {
                    const int rowl = cch * 64 + lrow4;
                    int rel = rel0 + rowl;
                    rel = rel < 0 ? 0 : (rel > RR - 1 ? RR - 1 : rel);
                    const char* rs = (const char*)rp2 + (((size_t)(n * RR + rel)) << 7) + lseg4;
                    uint32_t rd = uR + rowl * AST + lseg4;
                    CPA16(rd, rs); CPA16(rd + 16, rs + 16);
                }
            } else {
                int rel = rel0 + 128 + lrow4;
                rel = rel < 0 ? 0 : (rel > RR - 1 ? RR - 1 : rel);
                const int phys = (128 + roff) % 192 + lrow4;
                const char* rs = (const char*)rp2 + (((size_t)(n * RR + rel)) << 7) + lseg4;
                uint32_t rd = uR + phys * AST + lseg4;
                CPA16(rd, rs); CPA16(rd + 16, rs + 16);
            }
            CP_COMMIT();
            if (tid < 64)
                cc[tid] = c1g[(size_t)bn * LL + m0 + tid] * SCALE2F +
                          (pad[b * LL + m0 + tid] ? (-1.0e6f * LOG2E) : 0.0f);
            if (tid < 192) {
                int rel = rel0 + tid;
                rel = rel < 0 ? 0 : (rel > RR - 1 ? RR - 1 : rel);
                c2s[tid] = c2g[n * RR + rel];
            }
        }
        CP_WAIT(0);
        __syncthreads();

        // ---- band MMA: 5 np-tiles per warp (np = npi + 7 - w) ----
#pragma unroll
        for (int npi = 0; npi < 5; npi++) {
            const int np = npi + 7 - w;
            float b0[4] = {}, b1[4] = {};
            int pr16 = np * 16 + roff;
            if (pr16 >= 192) pr16 -= 192;
            const uint32_t rbase = (pr16 + brow) * AST + bk16;
#pragma unroll
            for (int ks = 0; ks < 4; ks++) {
                uint32_t bh[4];
                ldmx4(bh, uR + rbase + ks * 32);
                mma16816(b0, fqh[ks], bh + 0);
                mma16816(b1, fqh[ks], bh + 2);
            }
            const int pc   = npi * 16 + tg * 2;
            const int cidx = np * 16 + tg * 2;
            float* pr0 = pos + (w * 16 + g) * POSW2;
            float* pr1 = pos + (w * 16 + g + 8) * POSW2;
            const float ca = c2s[cidx],     cb = c2s[cidx + 1];
            const float cd = c2s[cidx + 8], ce = c2s[cidx + 9];
            *(float2*)(pr0 + pc)     = make_float2(b0[0] + ca, b0[1] + cb);
            *(float2*)(pr1 + pc)     = make_float2(b0[2] + ca, b0[3] + cb);
            *(float2*)(pr0 + pc + 8) = make_float2(b1[0] + cd, b1[1] + ce);
            *(float2*)(pr1 + pc + 8) = make_float2(b1[2] + cd, b1[3] + ce);
        }

        // ---- score MMA: S = qh . K^T ----
        float sfr[8][4] = {};
#pragma unroll
        for (int ks = 0; ks < 4; ks++) {
#pragma unroll
            for (int np = 0; np < 4; np++) {
                uint32_t bh[4];
                ldmx4(bh, uK + (np * 16 + brow) * AST + bk16 + ks * 32);
                mma16816(sfr[np * 2 + 0], fqh[ks], bh + 0);
                mma16816(sfr[np * 2 + 1], fqh[ks], bh + 2);
            }
        }
        __syncwarp();

        // ---- gather band + softmax ----
#pragma unroll
        for (int r2 = 0; r2 < 2; r2++) {
            const int ii = g + r2 * 8;
            const float* pr = pos + (w * 16 + ii) * POSW2 + (15 - ii);
            float mx = -INFINITY;
#pragma unroll
            for (int nt = 0; nt < 8; nt++) {
#pragma unroll
                for (int v2 = 0; v2 < 2; v2++) {
                    const int j = nt * 8 + tg * 2 + v2;
                    float t = fmaf(sfr[nt][r2 * 2 + v2] + pr[j], SCALE2F, cc[j]);
                    sfr[nt][r2 * 2 + v2] = t;
                    mx = fmaxf(mx, t);
                }
            }
            mx = fmaxf(mx, __shfl_xor_sync(0xffffffffu, mx, 1));
            mx = fmaxf(mx, __shfl_xor_sync(0xffffffffu, mx, 2));
            const float mnew = fmaxf(mrow[r2], mx);
            const float alpha = exp2p(mrow[r2] - mnew);
            mrow[r2] = mnew;
            float ssum = 0.f;
#pragma unroll
            for (int nt = 0; nt < 8; nt++) {
#pragma unroll
                for (int v2 = 0; v2 < 2; v2++) {
                    float p = exp2p(sfr[nt][r2 * 2 + v2] - mnew);
                    sfr[nt][r2 * 2 + v2] = p;
                    ssum += p;
                }
            }
            ssum += __shfl_xor_sync(0xffffffffu, ssum, 1);
            ssum += __shfl_xor_sync(0xffffffffu, ssum, 2);
            lrowv[r2] = lrowv[r2] * alpha + ssum;
#pragma unroll
            for (int ht = 0; ht < 8; ht++) {
                o[ht][r2 * 2 + 0] *= alpha;
                o[ht][r2 * 2 + 1] *= alpha;
            }
        }

        // ---- PV: O += P . V ----
#pragma unroll
        for (int ks = 0; ks < 4; ks++) {
            uint32_t aph[4];
#pragma unroll
            for (int q2 = 0; q2 < 2; q2++) {
                const float* f = sfr[2 * ks + q2];
                aph[q2 * 2 + 0] = pack_h2(f[0], f[1]);
                aph[q2 * 2 + 1] = pack_h2(f[2], f[3]);
            }
            const uint32_t vo = (ks * 16 + vrow) * AST + vsel;
#pragma unroll
            for (int hp = 0; hp < 4; hp++) {
                uint32_t vbh[4];
                ldmx4t(vbh, uV + vo + hp * 32);
                mma16816(o[hp * 2 + 0], aph, vbh + 0);
                mma16816(o[hp * 2 + 1], aph, vbh + 2);
            }
        }
    }

    // ---- epilogue: normalize, write [(b,l)][(n,h)] half2 pairs ----
#pragma unroll
    for (int r2 = 0; r2 < 2; r2++) {
        const int i = w * 16 + g + r2 * 8;
        const int rowg = b * LL + l0 + i;
        const float inv = 1.0f / lrowv[r2];
#pragma unroll
        for (int ht = 0; ht < 8; ht++) {
            float v0 = o[ht][r2 * 2 + 0] * inv;
            float v1 = o[ht][r2 * 2 + 1] * inv;
            const int col = n * 64 + ht * 8 + tg * 2;
            outp[(size_t)rowg * 512 + (col >> 1)] = pack_h2(v0, v1);
        }
    }
}

// ---------------------------------------------------------------------------
// LayerNorm
// ---------------------------------------------------------------------------
__global__ __launch_bounds__(256) void ln_kernel(
    float* __restrict__ X, const float* __restrict__ g, const float* __restrict__ bta)
{
    __shared__ float red[8];
    const int row = blockIdx.x;
    const int t   = threadIdx.x;
    float4 x = *(float4*)(X + (size_t)row * DD + t * 4);

    float s = x.x + x.y + x.z + x.w;
#pragma unroll
    for (int d = 16; d; d >>= 1) s += __shfl_xor_sync(0xffffffffu, s, d);
    if ((t & 31) == 0) red[t >> 5] = s;
    __syncthreads();
    float tot = red[0] + red[1] + red[2] + red[3] + red[4] + red[5] + red[6] + red[7];
    float mu = tot * (1.0f / DD);
    __syncthreads();

    float dx0 = x.x - mu, dx1 = x.y - mu, dx2 = x.z - mu, dx3 = x.w - mu;
    float sq = dx0 * dx0 + dx1 * dx1 + dx2 * dx2 + dx3 * dx3;
#pragma unroll
    for (int d = 16; d; d >>= 1) sq += __shfl_xor_sync(0xffffffffu, sq, d);
    if ((t & 31) == 0) red[t >> 5] = sq;
    __syncthreads();
    float var = (red[0] + red[1] + red[2] + red[3] + red[4] + red[5] + red[6] + red[7]) * (1.0f / DD);
    float rs = rsqrtf(var + 1e-5f);

    float4 gg = *(const float4*)(g + t * 4);
    float4 bb = *(const float4*)(bta + t * 4);
    float4 y = make_float4(dx0 * rs * gg.x + bb.x, dx1 * rs * gg.y + bb.y,
                           dx2 * rs * gg.z + bb.z, dx3 * rs * gg.w + bb.w);
    *(float4*)(X + (size_t)row * DD + t * 4) = y;
}

// ---------------------------------------------------------------------------
// Launch
// ---------------------------------------------------------------------------
extern "C" void kernel_launch(void* const* d_in, const int* in_sizes, int n_in,
                              void* d_out, int out_size)
{
    const float* q   = (const float*)d_in[0];
    const float* k   = (const float*)d_in[1];
    const float* v   = (const float*)d_in[2];
    const float* pe  = (const float*)d_in[3];
    const int*   pad = (const int*)d_in[4];
    const float* q_w = (const float*)d_in[5];
    const float* k_w = (const float*)d_in[6];
    const float* k_b = (const float*)d_in[7];
    const float* v_w = (const float*)d_in[8];
    const float* v_b = (const float*)d_in[9];
    const float* rwb = (const float*)d_in[10];
    const float* rrb = (const float*)d_in[11];
    const float* r_k = (const float*)d_in[12];
    const float* pw  = (const float*)d_in[13];
    const float* pb  = (const float*)d_in[14];
    const float* lg  = (const float*)d_in[15];
    const float* lb  = (const float*)d_in[16];
    float* out = (float*)d_out;

    cudaFuncSetAttribute(attn2, cudaFuncAttributeMaxDynamicSharedMemorySize, ATTN_BYTES);

    char *inp, *wtp;
    cudaGetSymbolAddress((void**)&inp, g_IN4);
    cudaGetSymbolAddress((void**)&wtp, g_WT4);
    uint32_t *qh2, *kh2, *vh2, *rp2;
    float *c1p, *c2p;
    cudaGetSymbolAddress((void**)&qh2, g_QH2);
    cudaGetSymbolAddress((void**)&kh2, g_KH2);
    cudaGetSymbolAddress((void**)&vh2, g_VH2);
    cudaGetSymbolAddress((void**)&rp2, g_RP2);
    cudaGetSymbolAddress((void**)&c1p, g_C1);
    cudaGetSymbolAddress((void**)&c2p, g_C2);

    dim3 gg(8, 32);
    dim3 tr(32, 8);
    const int n4_in = BB * LL * DD / 4;

    // ---- q projection -> qh (no bias) ----
    cvt_kernel<<<(n4_in + 255) / 256, 256>>>((const float4*)q, (uint32_t*)inp, n4_in);
    trcvt_kernel<<<dim3(32, 32, 1), tr>>>(q_w, (__half*)wtp, DD, DD);
    hgemm<<<gg, 256>>>(inp, wtp, nullptr, nullptr, nullptr, qh2, 1);
    // ---- k projection (+k_b) ----
    cvt_kernel<<<(n4_in + 255) / 256, 256>>>((const float4*)k, (uint32_t*)inp, n4_in);
    trcvt_kernel<<<dim3(32, 32, 1), tr>>>(k_w, (__half*)wtp, DD, DD);
    hgemm<<<gg, 256>>>(inp, wtp, k_b, nullptr, nullptr, kh2, 1);
    cdot_kernel<<<BB * NH * LL / 256, 256>>>(kh2, rwb, c1p, 10);
    // ---- v projection (+v_b) ----
    cvt_kernel<<<(n4_in + 255) / 256, 256>>>((const float4*)v, (uint32_t*)inp, n4_in);
    trcvt_kernel<<<dim3(32, 32, 1), tr>>>(v_w, (__half*)wtp, DD, DD);
    hgemm<<<gg, 256>>>(inp, wtp, v_b, nullptr, nullptr, vh2, 2);
    // ---- rp projection ----
    const int n4_pe = RR * DD / 4;
    cvt_kernel<<<(n4_pe + 255) / 256, 256>>>((const float4*)pe, (uint32_t*)inp, n4_pe);
    trcvt_kernel<<<dim3(2, 32, 16), tr>>>(r_k, (__half*)wtp, DD, HH);
    hgemm<<<dim3(8, 16), 256>>>(inp, wtp, nullptr, nullptr, nullptr, rp2, 4);
    cdot_kernel<<<NH * RR / 256, 256>>>(rp2, rrb, c2p, 11);
    // ---- attention (128 q-rows per CTA) ----
    attn2<<<dim3(LL / 128, BB * NH), 256, ATTN_BYTES>>>(pad, c1p, c2p, qh2,
                                                        kh2, vh2, rp2,
                                                        (uint32_t*)inp);
    // ---- post projection + residual ----
    trcvt_kernel<<<dim3(32, 32, 1), tr>>>(pw, (__half*)wtp, DD, DD);
    hgemm<<<gg, 256>>>(inp, wtp, pb, q, out, nullptr, 3);
    // ---- layernorm ----
    ln_kernel<<<BB * LL, 256>>>(out, lg, lb);
}